// round 14
// baseline (speedup 1.0000x reference)
#include <cuda_runtime.h>
#include <cuda_fp16.h>
#include <cstdint>

#define Bn    32
#define Cn    256
#define HWn   1024
#define NROWS 32768
#define Kn    1024
#define NTENS 8388608

// ---------------- scratch (device globals; no allocation allowed) ----------
__device__ __align__(16) __half g_Eh[Kn * Cn];        // 0.5MB fp16 emb
__device__ float  g_se[Kn];
__device__ unsigned long long g_best[NROWS];
__device__ int    g_outdone;
__device__ double g_loss;

// proxy quantization: q = floor((p + 0.8) * 40000), step 2.5e-5
#define QSCALE 40000.0f
#define QOFS   0.8f
#define QWIN   26u           // 6.5e-4 window in q-steps
#define CAP    16

// ---------------- PTX helpers ----------------------------------------------
__device__ __forceinline__ uint32_t cvta_s(const void* p) {
    return (uint32_t)__cvta_generic_to_shared(p);
}
__device__ __forceinline__ void cp16(uint32_t dst, const void* src) {
    asm volatile("cp.async.cg.shared.global [%0], [%1], 16;"
                 :: "r"(dst), "l"(src) : "memory");
}
__device__ __forceinline__ void cp_commit() {
    asm volatile("cp.async.commit_group;" ::: "memory");
}
template <int N> __device__ __forceinline__ void cp_wait() {
    asm volatile("cp.async.wait_group %0;" :: "n"(N) : "memory");
}
__device__ __forceinline__ void ldsm4(uint32_t* r, uint32_t a) {
    asm volatile("ldmatrix.sync.aligned.m8n8.x4.shared.b16 {%0,%1,%2,%3},[%4];"
                 : "=r"(r[0]), "=r"(r[1]), "=r"(r[2]), "=r"(r[3]) : "r"(a));
}
__device__ __forceinline__ void mma16816(float* c, const uint32_t* a, const uint32_t* b) {
    asm volatile(
        "mma.sync.aligned.m16n8k16.row.col.f32.f16.f16.f32 "
        "{%0,%1,%2,%3},{%4,%5,%6,%7},{%8,%9},{%0,%1,%2,%3};"
        : "+f"(c[0]), "+f"(c[1]), "+f"(c[2]), "+f"(c[3])
        : "r"(a[0]), "r"(a[1]), "r"(a[2]), "r"(a[3]), "r"(b[0]), "r"(b[1]));
}

// exact fp32 distance — identical value sequence to rounds 4-13 (zero flips):
// ascending c, groups of 4, fmaf order x,y,z,w. x read strided from [B,C,H,W].
__device__ __forceinline__ unsigned long long exact_key(
    const float* __restrict__ x, int row, const float* __restrict__ emb,
    float sx, int code) {
    const float* xb = x + (size_t)(row >> 10) * (Cn * HWn) + (row & 1023);
    const float4* er = (const float4*)(emb + (size_t)code * Cn);
    float acc = 0.f;
    #pragma unroll 8
    for (int c = 0; c < Cn / 4; c++) {
        float4 ev = __ldg(er + c);
        float x0 = __ldg(xb + (size_t)(4 * c + 0) * HWn);
        float x1 = __ldg(xb + (size_t)(4 * c + 1) * HWn);
        float x2 = __ldg(xb + (size_t)(4 * c + 2) * HWn);
        float x3 = __ldg(xb + (size_t)(4 * c + 3) * HWn);
        acc = fmaf(x0, ev.x, acc);
        acc = fmaf(x1, ev.y, acc);
        acc = fmaf(x2, ev.z, acc);
        acc = fmaf(x3, ev.w, acc);
    }
    float D = __fsub_rn(__fadd_rn(sx, g_se[code]), __fmul_rn(2.0f, acc));
    return ((unsigned long long)__float_as_uint(D) << 32) | (unsigned)code;
}

// ---------------------------------------------------------------------------
// Prep (emb only now): emb -> fp16 + se (fp64->fp32); reset counters.
// ---------------------------------------------------------------------------
__global__ void k_prepe(const float* __restrict__ emb) {
    int k = blockIdx.x * 256 + threadIdx.x;
    if (k == 0) { g_loss = 0.0; g_outdone = 0; }
    if (k >= Kn) return;
    const float* e = emb + (size_t)k * Cn;
    double s = 0.0;
    for (int g = 0; g < 32; g++) {
        float4 v0 = *(const float4*)(e + g * 8);
        float4 v1 = *(const float4*)(e + g * 8 + 4);
        float vv[8] = {v0.x, v0.y, v0.z, v0.w, v1.x, v1.y, v1.z, v1.w};
        __align__(16) __half hb[8];
        #pragma unroll
        for (int i = 0; i < 8; i++) {
            float v = vv[i];
            s += (double)v * (double)v;
            hb[i] = __float2half_rn(v);
        }
        *(uint4*)&g_Eh[(size_t)k * Cn + g * 8] = *(uint4*)hb;
    }
    g_se[k] = (float)s;
}

// ---------------------------------------------------------------------------
// Fused: x->fp16 A-tile prep (staged through SB) + pruning GEMM +
// incremental select + inline exact resolution.
// ---------------------------------------------------------------------------
#define SA_OFF    0
#define SB_OFF    65536
#define SES_OFF   (65536 + 32768)          // 98304, 4KB
#define SMIN_OFF  (SES_OFF + 4096)         // 102400, 512B
#define SCNT_OFF  (SMIN_OFF + 512)         // 102912, 512B
#define SLIST_OFF (SCNT_OFF + 512)         // 103424, 8KB
#define SSX_OFF   (SLIST_OFF + 128 * CAP * 4)   // 111616, 512B
#define SM_TOTAL  (SSX_OFF + 512)          // 112128 (x2 = 224256 <= 227KB)

__global__ __launch_bounds__(256, 2) void k_mma(const float* __restrict__ x,
                                                const float* __restrict__ emb) {
    extern __shared__ char sm[];
    const uint32_t smem = cvta_s(sm);
    float*    ses   = (float*)(sm + SES_OFF);
    uint32_t* smin  = (uint32_t*)(sm + SMIN_OFF);
    uint32_t* scnt  = (uint32_t*)(sm + SCNT_OFF);
    uint32_t* slist = (uint32_t*)(sm + SLIST_OFF);
    float*    sxs   = (float*)(sm + SSX_OFF);
    __shared__ int s_ncand, s_novf;

    const int tid  = threadIdx.x;
    const int lane = tid & 31;
    const int wid  = tid >> 5;
    const int wm   = wid & 3;
    const int wn   = wid >> 2;
    const int row0 = blockIdx.x * 128;

    for (int i = tid; i < Kn; i += 256) ses[i] = g_se[i];
    if (tid < 128) { smin[tid] = 0xffffffffu; scnt[tid] = 0; }
    if (tid == 0) { s_ncand = 0; s_novf = 0; }

    // ==== fused A prep: stage x fp32 half-chunks in SB, emit fp16 to SA ====
    {
        const int b   = row0 >> 10;
        const int hw0 = row0 & 1023;
        const float* xb = x + (size_t)b * (Cn * HWn) + hw0;
        const int hwme = tid >> 1;     // row this thread sums
        const int half = tid & 1;
        double sxd = 0.0;

        #define STAGE(H) do {                                                 \
            uint32_t _d = smem + SB_OFF + (uint32_t)((H) & 1) * 16384;        \
            _Pragma("unroll")                                                 \
            for (int _tt = 0; _tt < 4; _tt++) {                               \
                int _idx = tid + _tt * 256;                                   \
                int _cl = _idx >> 5, _seg = _idx & 31;                        \
                cp16(_d + _cl * 512 + _seg * 16,                              \
                     xb + (size_t)((H) * 32 + _cl) * HWn + _seg * 4);         \
            }                                                                 \
            cp_commit();                                                      \
        } while (0)

        STAGE(0);
        for (int h = 0; h < 8; h++) {
            if (h < 7) { STAGE(h + 1); cp_wait<1>(); }
            else       cp_wait<0>();
            __syncthreads();
            const float* sb = (const float*)(sm + SB_OFF + (h & 1) * 16384);
            #pragma unroll
            for (int g2 = 0; g2 < 2; g2++) {
                int g = half * 2 + g2;                 // group of 8 c within 32
                __align__(16) __half hb[8];
                #pragma unroll
                for (int i = 0; i < 8; i++) {
                    float v = sb[(g * 8 + i) * 128 + hwme];
                    sxd += (double)v * (double)v;
                    hb[i] = __float2half_rn(v);
                }
                int cglob = h * 32 + g * 8;
                int st = cglob >> 6;
                int kc = (cglob & 63) >> 3;
                uint32_t bo = (uint32_t)(hwme * 128 + kc * 16);
                *(uint4*)(sm + SA_OFF + st * 16384 +
                          (bo ^ ((bo >> 3) & 0x70))) = *(uint4*)hb;
            }
            __syncthreads();
        }
        #undef STAGE

        double so = __shfl_down_sync(0xffffffffu, sxd, 1);
        if (half == 0) sxs[hwme] = (float)(sxd + so);
    }
    __syncthreads();

    // ==== mainloop: B double-buffered, proxy + incremental select ====
    #define ISSUEB(T) do {                                                    \
        int _t = (T);                                                         \
        int _cb = _t >> 2, _s = _t & 3;                                       \
        const __half* _gb = g_Eh + (size_t)(_cb * 128) * Cn + _s * 64;        \
        uint32_t _b = smem + SB_OFF + (uint32_t)(_t & 1) * 16384;             \
        _Pragma("unroll")                                                     \
        for (int _tt = 0; _tt < 4; _tt++) {                                   \
            int _idx = tid + _tt * 256;                                       \
            int _r = _idx >> 3, _kc = _idx & 7;                               \
            uint32_t _bo = (uint32_t)(_r * 128 + _kc * 16);                   \
            cp16(_b + (_bo ^ ((_bo >> 3) & 0x70)),                            \
                 _gb + (size_t)_r * Cn + _kc * 8);                            \
        }                                                                     \
        cp_commit();                                                          \
    } while (0)

    ISSUEB(0);

    const int arow0 = wm * 32 + (lane & 15);
    const int akofs = (lane >> 4);
    const int bnofs = ((lane >> 4) << 3) + (lane & 7);
    const int bkofs = ((lane >> 3) & 1);

    float acc[2][8][4];
    #pragma unroll
    for (int i = 0; i < 2; i++)
        #pragma unroll
        for (int j = 0; j < 8; j++)
            #pragma unroll
            for (int c = 0; c < 4; c++) acc[i][j][c] = 0.f;

    for (int t = 0; t < 32; t++) {
        __syncthreads();
        if (t + 1 < 32) { ISSUEB(t + 1); cp_wait<1>(); }
        else           cp_wait<0>();
        __syncthreads();

        const int s = t & 3;
        const uint32_t sA = smem + SA_OFF + (uint32_t)s * 16384;
        const uint32_t sB = smem + SB_OFF + (uint32_t)(t & 1) * 16384;

        #pragma unroll
        for (int ks = 0; ks < 4; ks++) {
            uint32_t af[2][4], bf[4][4];
            #pragma unroll
            for (int i = 0; i < 2; i++) {
                int r = arow0 + i * 16;
                int kc = ks * 2 + akofs;
                ldsm4(af[i], sA + r * 128 + ((kc ^ (r & 7)) << 4));
            }
            #pragma unroll
            for (int p = 0; p < 4; p++) {
                int n = wn * 64 + p * 16 + bnofs;
                int kc = ks * 2 + bkofs;
                ldsm4(bf[p], sB + n * 128 + ((kc ^ (n & 7)) << 4));
            }
            #pragma unroll
            for (int i = 0; i < 2; i++)
                #pragma unroll
                for (int j = 0; j < 8; j++)
                    mma16816(acc[i][j], af[i], &bf[j >> 1][(j & 1) * 2]);
        }

        if (s == 3) {   // end of code-block cb: q -> running min + push
            const int cb = t >> 2;
            uint32_t lm[2][2] = {{0xffffffffu, 0xffffffffu},
                                 {0xffffffffu, 0xffffffffu}};
            #pragma unroll
            for (int i = 0; i < 2; i++) {
                #pragma unroll
                for (int j = 0; j < 8; j++) {
                    int ncode = cb * 128 + wn * 64 + j * 8 + (lane & 3) * 2;
                    #pragma unroll
                    for (int c = 0; c < 4; c++) {
                        float p = __fmaf_rn(-2.0f, acc[i][j][c], ses[ncode + (c & 1)]);
                        float qf = (p + QOFS) * QSCALE;
                        qf = fminf(fmaxf(qf, 0.f), 65535.f);
                        uint32_t qv = (uint32_t)qf;
                        lm[i][c >> 1] = min(lm[i][c >> 1], qv);
                        acc[i][j][c] = __uint_as_float(qv);
                    }
                }
                #pragma unroll
                for (int h = 0; h < 2; h++)
                    atomicMin(&smin[wm * 32 + i * 16 + h * 8 + (lane >> 2)], lm[i][h]);
            }
            __syncthreads();
            #pragma unroll
            for (int i = 0; i < 2; i++)
                #pragma unroll
                for (int j = 0; j < 8; j++) {
                    int ncode = cb * 128 + wn * 64 + j * 8 + (lane & 3) * 2;
                    #pragma unroll
                    for (int c = 0; c < 4; c++) {
                        uint32_t qv = __float_as_uint(acc[i][j][c]);
                        int rl = wm * 32 + i * 16 + (c >> 1) * 8 + (lane >> 2);
                        if (qv <= smin[rl] + QWIN) {
                            uint32_t idx = atomicAdd(&scnt[rl], 1u);
                            if (idx < CAP)
                                slist[rl * CAP + idx] =
                                    (qv << 10) | (uint32_t)(ncode + (c & 1));
                        }
                        acc[i][j][c] = 0.f;
                    }
                }
        }
    }
    #undef ISSUEB

    // ---- tail: refilter, then inline exact resolution (CTA-parallel) ----
    __syncthreads();
    uint32_t* cl = (uint32_t*)sm;                               // candidates
    unsigned long long* bb = (unsigned long long*)(sm + 16384); // per-row best
    int* ovf = (int*)(sm + 24576);                              // overflow rows

    if (tid < 128) {
        bb[tid] = ~0ull;
        uint32_t cnt = scnt[tid];
        if (cnt > CAP) {
            ovf[atomicAdd(&s_novf, 1)] = tid;
        } else {
            uint32_t thr = smin[tid] + QWIN;
            uint32_t tmp[CAP];
            int o = 0;
            for (uint32_t e = 0; e < cnt; e++) {
                uint32_t v = slist[tid * CAP + e];
                if ((v >> 10) <= thr)
                    tmp[o++] = ((uint32_t)tid << 10) | (v & 1023u);
            }
            if (o == 1) {
                bb[tid] = (unsigned long long)(tmp[0] & 1023u);  // certified
            } else {
                int base = atomicAdd(&s_ncand, o);
                for (int e = 0; e < o; e++) cl[base + e] = tmp[e];
            }
        }
    }
    __syncthreads();

    const int nc = s_ncand;
    for (int i = tid; i < nc; i += 256) {
        uint32_t rc = cl[i];
        int rl = rc >> 10, code = rc & 1023;
        unsigned long long key = exact_key(x, row0 + rl, emb, sxs[rl], code);
        atomicMin(&bb[rl], key);
    }
    const int nov = s_novf;
    for (int v = 0; v < nov; v++) {          // expected zero iterations
        int rl = ovf[v];
        for (int code = tid; code < Kn; code += 256) {
            unsigned long long key = exact_key(x, row0 + rl, emb, sxs[rl], code);
            atomicMin(&bb[rl], key);
        }
    }
    __syncthreads();
    if (tid < 128) g_best[row0 + tid] = bb[tid];
}

// ---------------------------------------------------------------------------
// Output: gather codes, write [B,C,H,W], accumulate MSE; last block finalizes.
// ---------------------------------------------------------------------------
__global__ __launch_bounds__(256)
void k_output(const float* __restrict__ x, const float* __restrict__ emb,
              float* __restrict__ out, int write_tensor,
              int loss_pos, int write_loss) {
    int blk = blockIdx.x;
    int b   = blk >> 4;
    int hw0 = (blk & 15) * 64;
    int tid = threadIdx.x;
    int h4  = tid & 15;
    int cgv = tid >> 4;
    int hw  = hw0 + h4 * 4;
    int n0  = b * HWn + hw;
    int i0 = (int)(g_best[n0]     & 0xffffffffu) & 1023;
    int i1 = (int)(g_best[n0 + 1] & 0xffffffffu) & 1023;
    int i2 = (int)(g_best[n0 + 2] & 0xffffffffu) & 1023;
    int i3 = (int)(g_best[n0 + 3] & 0xffffffffu) & 1023;
    const float* xb = x   + (size_t)b * (Cn * HWn) + hw;
    float*       ob = out + (size_t)b * (Cn * HWn) + hw;

    float accl = 0.f;
    #pragma unroll 4
    for (int cc = 0; cc < 16; cc++) {
        int c = cgv * 16 + cc;
        float q0 = emb[i0 * Cn + c];
        float q1 = emb[i1 * Cn + c];
        float q2 = emb[i2 * Cn + c];
        float q3 = emb[i3 * Cn + c];
        float4 xv = *(const float4*)&xb[c * HWn];
        float d0 = q0 - xv.x, d1 = q1 - xv.y, d2 = q2 - xv.z, d3 = q3 - xv.w;
        accl += d0 * d0 + d1 * d1 + d2 * d2 + d3 * d3;
        if (write_tensor) {
            float4 qv = make_float4(q0, q1, q2, q3);
            *(float4*)&ob[c * HWn] = qv;
        }
    }
    __shared__ float red[256];
    red[tid] = accl;
    __syncthreads();
    for (int s = 128; s; s >>= 1) {
        if (tid < s) red[tid] += red[tid + s];
        __syncthreads();
    }
    if (tid == 0) {
        atomicAdd(&g_loss, (double)red[0]);
        __threadfence();
        int d = atomicAdd(&g_outdone, 1);
        if (d == (int)gridDim.x - 1) {
            if (write_loss)
                out[loss_pos] = (float)(1.25 * g_loss / (double)NTENS);
            g_outdone = 0;   // reset for next graph replay
            g_loss = 0.0;
        }
    }
}

// ---------------------------------------------------------------------------
extern "C" void kernel_launch(void* const* d_in, const int* in_sizes, int n_in,
                              void* d_out, int out_size) {
    const float* x   = (const float*)d_in[0];
    const float* emb = (const float*)d_in[1];
    float* out = (float*)d_out;

    cudaFuncSetAttribute(k_mma, cudaFuncAttributeMaxDynamicSharedMemorySize, SM_TOTAL);

    k_prepe<<<4, 256>>>(emb);
    k_mma<<<NROWS / 128, 256, SM_TOTAL>>>(x, emb);

    int write_tensor = (out_size >= NTENS) ? 1 : 0;
    int write_loss   = (out_size == NTENS + 1 || out_size == 1) ? 1 : 0;
    int loss_pos     = (out_size == NTENS + 1) ? NTENS : 0;
    k_output<<<512, 256>>>(x, emb, out, write_tensor, loss_pos, write_loss);
}

// round 15
// speedup vs baseline: 1.2375x; 1.2375x over previous
#include <cuda_runtime.h>
#include <cuda_fp16.h>
#include <cstdint>

#define Bn    32
#define Cn    256
#define HWn   1024
#define NROWS 32768
#define Kn    1024
#define NTENS 8388608

// ---------------- scratch (device globals; no allocation allowed) ----------
__device__ __align__(16) __half g_Eh[Kn * Cn];        // 0.5MB fp16 emb
__device__ float  g_se[Kn];
__device__ unsigned long long g_best[NROWS];
__device__ int    g_outdone;
__device__ double g_loss;

// proxy quantization: q = floor((p + 0.8) * 40000), step 2.5e-5
#define QSCALE 40000.0f
#define QOFS   0.8f
#define QWIN   26u           // 6.5e-4 window in q-steps
#define CAP    16

// ---------------- PTX helpers ----------------------------------------------
__device__ __forceinline__ uint32_t cvta_s(const void* p) {
    return (uint32_t)__cvta_generic_to_shared(p);
}
__device__ __forceinline__ void cp16(uint32_t dst, const void* src) {
    asm volatile("cp.async.cg.shared.global [%0], [%1], 16;"
                 :: "r"(dst), "l"(src) : "memory");
}
__device__ __forceinline__ void cp_commit() {
    asm volatile("cp.async.commit_group;" ::: "memory");
}
template <int N> __device__ __forceinline__ void cp_wait() {
    asm volatile("cp.async.wait_group %0;" :: "n"(N) : "memory");
}
__device__ __forceinline__ void ldsm4(uint32_t* r, uint32_t a) {
    asm volatile("ldmatrix.sync.aligned.m8n8.x4.shared.b16 {%0,%1,%2,%3},[%4];"
                 : "=r"(r[0]), "=r"(r[1]), "=r"(r[2]), "=r"(r[3]) : "r"(a));
}
__device__ __forceinline__ void mma16816(float* c, const uint32_t* a, const uint32_t* b) {
    asm volatile(
        "mma.sync.aligned.m16n8k16.row.col.f32.f16.f16.f32 "
        "{%0,%1,%2,%3},{%4,%5,%6,%7},{%8,%9},{%0,%1,%2,%3};"
        : "+f"(c[0]), "+f"(c[1]), "+f"(c[2]), "+f"(c[3])
        : "r"(a[0]), "r"(a[1]), "r"(a[2]), "r"(a[3]), "r"(b[0]), "r"(b[1]));
}

// exact fp32 distance — identical value sequence to rounds 4-14 (zero flips):
// ascending c, groups of 4, fmaf order x,y,z,w. x read strided from [B,C,H,W].
__device__ __forceinline__ unsigned long long exact_key(
    const float* __restrict__ x, int row, const float* __restrict__ emb,
    float sx, int code) {
    const float* xb = x + (size_t)(row >> 10) * (Cn * HWn) + (row & 1023);
    const float4* er = (const float4*)(emb + (size_t)code * Cn);
    float acc = 0.f;
    #pragma unroll 8
    for (int c = 0; c < Cn / 4; c++) {
        float4 ev = __ldg(er + c);
        float x0 = __ldg(xb + (size_t)(4 * c + 0) * HWn);
        float x1 = __ldg(xb + (size_t)(4 * c + 1) * HWn);
        float x2 = __ldg(xb + (size_t)(4 * c + 2) * HWn);
        float x3 = __ldg(xb + (size_t)(4 * c + 3) * HWn);
        acc = fmaf(x0, ev.x, acc);
        acc = fmaf(x1, ev.y, acc);
        acc = fmaf(x2, ev.z, acc);
        acc = fmaf(x3, ev.w, acc);
    }
    float D = __fsub_rn(__fadd_rn(sx, g_se[code]), __fmul_rn(2.0f, acc));
    return ((unsigned long long)__float_as_uint(D) << 32) | (unsigned)code;
}

// ---------------------------------------------------------------------------
// Prep (emb only): warp per code, lanes over channels, fp64 butterfly sum.
// Chain depth ~13 instead of 2048 -> latency-bound no more.
// ---------------------------------------------------------------------------
__global__ __launch_bounds__(256) void k_prepe(const float* __restrict__ emb) {
    const int lane = threadIdx.x & 31;
    const int k = (blockIdx.x * 256 + threadIdx.x) >> 5;   // warp id = code
    if (blockIdx.x == 0 && threadIdx.x == 0) { g_loss = 0.0; g_outdone = 0; }
    if (k >= Kn) return;
    const float* e = emb + (size_t)k * Cn;
    float4 a = __ldg((const float4*)(e + lane * 8));
    float4 b = __ldg((const float4*)(e + lane * 8 + 4));
    float vv[8] = {a.x, a.y, a.z, a.w, b.x, b.y, b.z, b.w};
    double s = 0.0;
    __align__(16) __half hb[8];
    #pragma unroll
    for (int i = 0; i < 8; i++) {
        double v = (double)vv[i];
        s += v * v;
        hb[i] = __float2half_rn(vv[i]);
    }
    *(uint4*)&g_Eh[(size_t)k * Cn + lane * 8] = *(uint4*)hb;
    #pragma unroll
    for (int o = 16; o; o >>= 1) s += __shfl_xor_sync(0xffffffffu, s, o);
    if (lane == 0) g_se[k] = (float)s;
}

// ---------------------------------------------------------------------------
// Fused: x->fp16 A-tile prep (staged through SB) + pruning GEMM +
// incremental select + inline exact resolution. (round-14 proven code)
// ---------------------------------------------------------------------------
#define SA_OFF    0
#define SB_OFF    65536
#define SES_OFF   (65536 + 32768)          // 98304, 4KB
#define SMIN_OFF  (SES_OFF + 4096)         // 102400, 512B
#define SCNT_OFF  (SMIN_OFF + 512)         // 102912, 512B
#define SLIST_OFF (SCNT_OFF + 512)         // 103424, 8KB
#define SSX_OFF   (SLIST_OFF + 128 * CAP * 4)   // 111616, 512B
#define SM_TOTAL  (SSX_OFF + 512)          // 112128 (x2 = 224256 <= 227KB)

__global__ __launch_bounds__(256, 2) void k_mma(const float* __restrict__ x,
                                                const float* __restrict__ emb) {
    extern __shared__ char sm[];
    const uint32_t smem = cvta_s(sm);
    float*    ses   = (float*)(sm + SES_OFF);
    uint32_t* smin  = (uint32_t*)(sm + SMIN_OFF);
    uint32_t* scnt  = (uint32_t*)(sm + SCNT_OFF);
    uint32_t* slist = (uint32_t*)(sm + SLIST_OFF);
    float*    sxs   = (float*)(sm + SSX_OFF);
    __shared__ int s_ncand, s_novf;

    const int tid  = threadIdx.x;
    const int lane = tid & 31;
    const int wid  = tid >> 5;
    const int wm   = wid & 3;
    const int wn   = wid >> 2;
    const int row0 = blockIdx.x * 128;

    for (int i = tid; i < Kn; i += 256) ses[i] = g_se[i];
    if (tid < 128) { smin[tid] = 0xffffffffu; scnt[tid] = 0; }
    if (tid == 0) { s_ncand = 0; s_novf = 0; }

    // ==== fused A prep: stage x fp32 half-chunks in SB, emit fp16 to SA ====
    {
        const int b   = row0 >> 10;
        const int hw0 = row0 & 1023;
        const float* xb = x + (size_t)b * (Cn * HWn) + hw0;
        const int hwme = tid >> 1;     // row this thread sums
        const int half = tid & 1;
        double sxd = 0.0;

        #define STAGE(H) do {                                                 \
            uint32_t _d = smem + SB_OFF + (uint32_t)((H) & 1) * 16384;        \
            _Pragma("unroll")                                                 \
            for (int _tt = 0; _tt < 4; _tt++) {                               \
                int _idx = tid + _tt * 256;                                   \
                int _cl = _idx >> 5, _seg = _idx & 31;                        \
                cp16(_d + _cl * 512 + _seg * 16,                              \
                     xb + (size_t)((H) * 32 + _cl) * HWn + _seg * 4);         \
            }                                                                 \
            cp_commit();                                                      \
        } while (0)

        STAGE(0);
        for (int h = 0; h < 8; h++) {
            if (h < 7) { STAGE(h + 1); cp_wait<1>(); }
            else       cp_wait<0>();
            __syncthreads();
            const float* sb = (const float*)(sm + SB_OFF + (h & 1) * 16384);
            #pragma unroll
            for (int g2 = 0; g2 < 2; g2++) {
                int g = half * 2 + g2;                 // group of 8 c within 32
                __align__(16) __half hb[8];
                #pragma unroll
                for (int i = 0; i < 8; i++) {
                    float v = sb[(g * 8 + i) * 128 + hwme];
                    sxd += (double)v * (double)v;
                    hb[i] = __float2half_rn(v);
                }
                int cglob = h * 32 + g * 8;
                int st = cglob >> 6;
                int kc = (cglob & 63) >> 3;
                uint32_t bo = (uint32_t)(hwme * 128 + kc * 16);
                *(uint4*)(sm + SA_OFF + st * 16384 +
                          (bo ^ ((bo >> 3) & 0x70))) = *(uint4*)hb;
            }
            __syncthreads();
        }
        #undef STAGE

        double so = __shfl_down_sync(0xffffffffu, sxd, 1);
        if (half == 0) sxs[hwme] = (float)(sxd + so);
    }
    __syncthreads();

    // ==== mainloop: B double-buffered, proxy + incremental select ====
    #define ISSUEB(T) do {                                                    \
        int _t = (T);                                                         \
        int _cb = _t >> 2, _s = _t & 3;                                       \
        const __half* _gb = g_Eh + (size_t)(_cb * 128) * Cn + _s * 64;        \
        uint32_t _b = smem + SB_OFF + (uint32_t)(_t & 1) * 16384;             \
        _Pragma("unroll")                                                     \
        for (int _tt = 0; _tt < 4; _tt++) {                                   \
            int _idx = tid + _tt * 256;                                       \
            int _r = _idx >> 3, _kc = _idx & 7;                               \
            uint32_t _bo = (uint32_t)(_r * 128 + _kc * 16);                   \
            cp16(_b + (_bo ^ ((_bo >> 3) & 0x70)),                            \
                 _gb + (size_t)_r * Cn + _kc * 8);                            \
        }                                                                     \
        cp_commit();                                                          \
    } while (0)

    ISSUEB(0);

    const int arow0 = wm * 32 + (lane & 15);
    const int akofs = (lane >> 4);
    const int bnofs = ((lane >> 4) << 3) + (lane & 7);
    const int bkofs = ((lane >> 3) & 1);

    float acc[2][8][4];
    #pragma unroll
    for (int i = 0; i < 2; i++)
        #pragma unroll
        for (int j = 0; j < 8; j++)
            #pragma unroll
            for (int c = 0; c < 4; c++) acc[i][j][c] = 0.f;

    for (int t = 0; t < 32; t++) {
        __syncthreads();
        if (t + 1 < 32) { ISSUEB(t + 1); cp_wait<1>(); }
        else           cp_wait<0>();
        __syncthreads();

        const int s = t & 3;
        const uint32_t sA = smem + SA_OFF + (uint32_t)s * 16384;
        const uint32_t sB = smem + SB_OFF + (uint32_t)(t & 1) * 16384;

        #pragma unroll
        for (int ks = 0; ks < 4; ks++) {
            uint32_t af[2][4], bf[4][4];
            #pragma unroll
            for (int i = 0; i < 2; i++) {
                int r = arow0 + i * 16;
                int kc = ks * 2 + akofs;
                ldsm4(af[i], sA + r * 128 + ((kc ^ (r & 7)) << 4));
            }
            #pragma unroll
            for (int p = 0; p < 4; p++) {
                int n = wn * 64 + p * 16 + bnofs;
                int kc = ks * 2 + bkofs;
                ldsm4(bf[p], sB + n * 128 + ((kc ^ (n & 7)) << 4));
            }
            #pragma unroll
            for (int i = 0; i < 2; i++)
                #pragma unroll
                for (int j = 0; j < 8; j++)
                    mma16816(acc[i][j], af[i], &bf[j >> 1][(j & 1) * 2]);
        }

        if (s == 3) {   // end of code-block cb: q -> running min + push
            const int cb = t >> 2;
            uint32_t lm[2][2] = {{0xffffffffu, 0xffffffffu},
                                 {0xffffffffu, 0xffffffffu}};
            #pragma unroll
            for (int i = 0; i < 2; i++) {
                #pragma unroll
                for (int j = 0; j < 8; j++) {
                    int ncode = cb * 128 + wn * 64 + j * 8 + (lane & 3) * 2;
                    #pragma unroll
                    for (int c = 0; c < 4; c++) {
                        float p = __fmaf_rn(-2.0f, acc[i][j][c], ses[ncode + (c & 1)]);
                        float qf = (p + QOFS) * QSCALE;
                        qf = fminf(fmaxf(qf, 0.f), 65535.f);
                        uint32_t qv = (uint32_t)qf;
                        lm[i][c >> 1] = min(lm[i][c >> 1], qv);
                        acc[i][j][c] = __uint_as_float(qv);
                    }
                }
                #pragma unroll
                for (int h = 0; h < 2; h++)
                    atomicMin(&smin[wm * 32 + i * 16 + h * 8 + (lane >> 2)], lm[i][h]);
            }
            __syncthreads();
            #pragma unroll
            for (int i = 0; i < 2; i++)
                #pragma unroll
                for (int j = 0; j < 8; j++) {
                    int ncode = cb * 128 + wn * 64 + j * 8 + (lane & 3) * 2;
                    #pragma unroll
                    for (int c = 0; c < 4; c++) {
                        uint32_t qv = __float_as_uint(acc[i][j][c]);
                        int rl = wm * 32 + i * 16 + (c >> 1) * 8 + (lane >> 2);
                        if (qv <= smin[rl] + QWIN) {
                            uint32_t idx = atomicAdd(&scnt[rl], 1u);
                            if (idx < CAP)
                                slist[rl * CAP + idx] =
                                    (qv << 10) | (uint32_t)(ncode + (c & 1));
                        }
                        acc[i][j][c] = 0.f;
                    }
                }
        }
    }
    #undef ISSUEB

    // ---- tail: refilter, then inline exact resolution (CTA-parallel) ----
    __syncthreads();
    uint32_t* cl = (uint32_t*)sm;                               // candidates
    unsigned long long* bb = (unsigned long long*)(sm + 16384); // per-row best
    int* ovf = (int*)(sm + 24576);                              // overflow rows

    if (tid < 128) {
        bb[tid] = ~0ull;
        uint32_t cnt = scnt[tid];
        if (cnt > CAP) {
            ovf[atomicAdd(&s_novf, 1)] = tid;
        } else {
            uint32_t thr = smin[tid] + QWIN;
            uint32_t tmp[CAP];
            int o = 0;
            for (uint32_t e = 0; e < cnt; e++) {
                uint32_t v = slist[tid * CAP + e];
                if ((v >> 10) <= thr)
                    tmp[o++] = ((uint32_t)tid << 10) | (v & 1023u);
            }
            if (o == 1) {
                bb[tid] = (unsigned long long)(tmp[0] & 1023u);  // certified
            } else {
                int base = atomicAdd(&s_ncand, o);
                for (int e = 0; e < o; e++) cl[base + e] = tmp[e];
            }
        }
    }
    __syncthreads();

    const int nc = s_ncand;
    for (int i = tid; i < nc; i += 256) {
        uint32_t rc = cl[i];
        int rl = rc >> 10, code = rc & 1023;
        unsigned long long key = exact_key(x, row0 + rl, emb, sxs[rl], code);
        atomicMin(&bb[rl], key);
    }
    const int nov = s_novf;
    for (int v = 0; v < nov; v++) {          // expected zero iterations
        int rl = ovf[v];
        for (int code = tid; code < Kn; code += 256) {
            unsigned long long key = exact_key(x, row0 + rl, emb, sxs[rl], code);
            atomicMin(&bb[rl], key);
        }
    }
    __syncthreads();
    if (tid < 128) g_best[row0 + tid] = bb[tid];
}

// ---------------------------------------------------------------------------
// Output: gather codes, write [B,C,H,W], accumulate MSE; last block finalizes.
// ---------------------------------------------------------------------------
__global__ __launch_bounds__(256)
void k_output(const float* __restrict__ x, const float* __restrict__ emb,
              float* __restrict__ out, int write_tensor,
              int loss_pos, int write_loss) {
    int blk = blockIdx.x;
    int b   = blk >> 4;
    int hw0 = (blk & 15) * 64;
    int tid = threadIdx.x;
    int h4  = tid & 15;
    int cgv = tid >> 4;
    int hw  = hw0 + h4 * 4;
    int n0  = b * HWn + hw;
    int i0 = (int)(g_best[n0]     & 0xffffffffu) & 1023;
    int i1 = (int)(g_best[n0 + 1] & 0xffffffffu) & 1023;
    int i2 = (int)(g_best[n0 + 2] & 0xffffffffu) & 1023;
    int i3 = (int)(g_best[n0 + 3] & 0xffffffffu) & 1023;
    const float* xb = x   + (size_t)b * (Cn * HWn) + hw;
    float*       ob = out + (size_t)b * (Cn * HWn) + hw;

    float accl = 0.f;
    #pragma unroll 4
    for (int cc = 0; cc < 16; cc++) {
        int c = cgv * 16 + cc;
        float q0 = emb[i0 * Cn + c];
        float q1 = emb[i1 * Cn + c];
        float q2 = emb[i2 * Cn + c];
        float q3 = emb[i3 * Cn + c];
        float4 xv = *(const float4*)&xb[c * HWn];
        float d0 = q0 - xv.x, d1 = q1 - xv.y, d2 = q2 - xv.z, d3 = q3 - xv.w;
        accl += d0 * d0 + d1 * d1 + d2 * d2 + d3 * d3;
        if (write_tensor) {
            float4 qv = make_float4(q0, q1, q2, q3);
            *(float4*)&ob[c * HWn] = qv;
        }
    }
    __shared__ float red[256];
    red[tid] = accl;
    __syncthreads();
    for (int s = 128; s; s >>= 1) {
        if (tid < s) red[tid] += red[tid + s];
        __syncthreads();
    }
    if (tid == 0) {
        atomicAdd(&g_loss, (double)red[0]);
        __threadfence();
        int d = atomicAdd(&g_outdone, 1);
        if (d == (int)gridDim.x - 1) {
            if (write_loss)
                out[loss_pos] = (float)(1.25 * g_loss / (double)NTENS);
            g_outdone = 0;   // reset for next graph replay
            g_loss = 0.0;
        }
    }
}

// ---------------------------------------------------------------------------
extern "C" void kernel_launch(void* const* d_in, const int* in_sizes, int n_in,
                              void* d_out, int out_size) {
    const float* x   = (const float*)d_in[0];
    const float* emb = (const float*)d_in[1];
    float* out = (float*)d_out;

    cudaFuncSetAttribute(k_mma, cudaFuncAttributeMaxDynamicSharedMemorySize, SM_TOTAL);

    k_prepe<<<128, 256>>>(emb);
    k_mma<<<NROWS / 128, 256, SM_TOTAL>>>(x, emb);

    int write_tensor = (out_size >= NTENS) ? 1 : 0;
    int write_loss   = (out_size == NTENS + 1 || out_size == 1) ? 1 : 0;
    int loss_pos     = (out_size == NTENS + 1) ? NTENS : 0;
    k_output<<<512, 256>>>(x, emb, out, write_tensor, loss_pos, write_loss);
}